// round 9
// baseline (speedup 1.0000x reference)
#include <cuda_runtime.h>
#include <math.h>

#define THREADS 256
#define RPT 4          // rows per thread (2 packed pairs)
#define KC 32          // codebook size
#define DD 8           // codebook dim

__device__ double g_sum;                 // zero-init at load; reset by last block each run
__device__ unsigned int g_counts[KC];
__device__ unsigned int g_done;

static __device__ __forceinline__ unsigned long long pk2(float lo, float hi) {
    unsigned long long r;
    asm("mov.b64 %0, {%1,%2};" : "=l"(r) : "f"(lo), "f"(hi));
    return r;
}
static __device__ __forceinline__ void upk2(unsigned long long v, float& lo, float& hi) {
    asm("mov.b64 {%0,%1}, %2;" : "=f"(lo), "=f"(hi) : "l"(v));
}
// packed f32x2 fma: d.lo = a.lo*b.lo + c.lo ; d.hi = a.hi*b.hi + c.hi
static __device__ __forceinline__ unsigned long long ffma2(unsigned long long a,
                                                           unsigned long long b,
                                                           unsigned long long c) {
    unsigned long long r;
    asm("fma.rn.f32x2 %0, %1, %2, %3;" : "=l"(r) : "l"(a), "l"(b), "l"(c));
    return r;
}
static __device__ __forceinline__ unsigned long long add2(unsigned long long a,
                                                          unsigned long long b) {
    unsigned long long r;
    asm("add.rn.f32x2 %0, %1, %2;" : "=l"(r) : "l"(a), "l"(b));
    return r;
}

__global__ __launch_bounds__(THREADS) void vq_fused(
    const float* __restrict__ z, const float* __restrict__ cb,
    float* __restrict__ out, int nrows, long long ndelem, int write_scalars)
{
    // per code k: q[0..3] = 4x ulonglong2 = 8 packed (-2c,-2c) coeffs,
    //             q[4].x = (||c||^2, ||c||^2), q[4].y unused.
    // Read as 5 LDS.128 (broadcast, conflict-free).
    __shared__ ulonglong2 s_ck[KC][5];
    __shared__ float2 s_cpair[KC][5];               // row as 4 float2, stride 5 -> conflict-free gather
    __shared__ unsigned int s_cnt[KC];
    __shared__ double s_red[THREADS / 32];
    __shared__ int s_islast;

    const int tid = threadIdx.x;
    const int lane = tid & 31;

    if (tid < KC) {
        float v[DD];
        float cn = 0.f;
#pragma unroll
        for (int d = 0; d < DD; d++) {
            v[d] = cb[tid * DD + d];
            cn = fmaf(v[d], v[d], cn);
        }
#pragma unroll
        for (int j = 0; j < 4; j++) {
            float m0 = -2.f * v[2 * j];
            float m1 = -2.f * v[2 * j + 1];
            ulonglong2 q;
            q.x = pk2(m0, m0);
            q.y = pk2(m1, m1);
            s_ck[tid][j] = q;
            s_cpair[tid][j] = make_float2(v[2 * j], v[2 * j + 1]);
        }
        ulonglong2 qn;
        qn.x = pk2(cn, cn);
        qn.y = 0ULL;
        s_ck[tid][4] = qn;
        s_cnt[tid] = 0u;
    }
    __syncthreads();

    const long long base = (long long)blockIdx.x * (THREADS * RPT) + tid;

    // ---- load 4 rows, pack two rows per 64-bit lane pair ----
    unsigned long long zp[RPT / 2][DD];
    bool valid[RPT];
#pragma unroll
    for (int p = 0; p < RPT / 2; ++p) {
        long long ra = base + (long long)(2 * p) * THREADS;
        long long rb = ra + THREADS;
        valid[2 * p]     = (ra < nrows);
        valid[2 * p + 1] = (rb < nrows);
        long long la = valid[2 * p] ? ra : 0;
        long long lb = valid[2 * p + 1] ? rb : 0;
        float4 a0 = __ldcs((const float4*)(z + la * DD));
        float4 a1 = __ldcs((const float4*)(z + la * DD + 4));
        float4 b0 = __ldcs((const float4*)(z + lb * DD));
        float4 b1 = __ldcs((const float4*)(z + lb * DD + 4));
        zp[p][0] = pk2(a0.x, b0.x); zp[p][1] = pk2(a0.y, b0.y);
        zp[p][2] = pk2(a0.z, b0.z); zp[p][3] = pk2(a0.w, b0.w);
        zp[p][4] = pk2(a1.x, b1.x); zp[p][5] = pk2(a1.y, b1.y);
        zp[p][6] = pk2(a1.z, b1.z); zp[p][7] = pk2(a1.w, b1.w);
    }

    float best[RPT];
    int   bi[RPT];
#pragma unroll
    for (int i = 0; i < RPT; i++) { best[i] = 3.4e38f; bi[i] = 0; }

    // ---- argmin over 32 codes: dist-z2 = ||c||^2 + sum((-2c_d) z_d)
    //      two 4-deep ffma2 chains + 1 add2 per pair (halved critical path) ----
#pragma unroll 4
    for (int k = 0; k < KC; k++) {
        ulonglong2 q0 = s_ck[k][0];   // c0, c1
        ulonglong2 q1 = s_ck[k][1];   // c2, c3
        ulonglong2 q2 = s_ck[k][2];   // c4, c5
        ulonglong2 q3 = s_ck[k][3];   // c6, c7
        ulonglong2 qn = s_ck[k][4];   // cn, -
#pragma unroll
        for (int p = 0; p < RPT / 2; p++) {
            unsigned long long accA = ffma2(zp[p][0], q0.x, qn.x);
            unsigned long long accB = ffma2(zp[p][1], q0.y, 0ULL);
            accA = ffma2(zp[p][2], q1.x, accA);
            accB = ffma2(zp[p][3], q1.y, accB);
            accA = ffma2(zp[p][4], q2.x, accA);
            accB = ffma2(zp[p][5], q2.y, accB);
            accA = ffma2(zp[p][6], q3.x, accA);
            accB = ffma2(zp[p][7], q3.y, accB);
            unsigned long long dist = add2(accA, accB);
            float da, db;
            upk2(dist, da, db);
            if (da < best[2 * p])     { best[2 * p] = da;     bi[2 * p] = k; }
            if (db < best[2 * p + 1]) { best[2 * p + 1] = db; bi[2 * p + 1] = k; }
        }
    }

    // ---- epilogue: explicit loss Σ(c−z)^2 (no cancellation), out = z + (c − z),
    //      warp-aggregated histogram ----
    float lsum = 0.f;
#pragma unroll
    for (int p = 0; p < RPT / 2; p++) {
        const int ba = bi[2 * p], bb = bi[2 * p + 1];
        float2 a0 = s_cpair[ba][0], a1 = s_cpair[ba][1],
               a2 = s_cpair[ba][2], a3 = s_cpair[ba][3];
        float2 b0 = s_cpair[bb][0], b1 = s_cpair[bb][1],
               b2 = s_cpair[bb][2], b3 = s_cpair[bb][3];
        float ca[DD] = {a0.x, a0.y, a1.x, a1.y, a2.x, a2.y, a3.x, a3.y};
        float cbv[DD] = {b0.x, b0.y, b1.x, b1.y, b2.x, b2.y, b3.x, b3.y};
        float oa[DD], ob[DD];
        float sa = 0.f, sb = 0.f;
#pragma unroll
        for (int d = 0; d < DD; d++) {
            float zlo, zhi;
            upk2(zp[p][d], zlo, zhi);
            float da = ca[d] - zlo;
            float db = cbv[d] - zhi;
            oa[d] = zlo + da;     // z + (z_q - z), matches reference FP order
            ob[d] = zhi + db;
            sa = fmaf(da, da, sa);
            sb = fmaf(db, db, sb);
        }
        long long ra = base + (long long)(2 * p) * THREADS;
        if (valid[2 * p]) {
            lsum += sa;
            __stcs((float4*)(out + ra * DD),     make_float4(oa[0], oa[1], oa[2], oa[3]));
            __stcs((float4*)(out + ra * DD + 4), make_float4(oa[4], oa[5], oa[6], oa[7]));
        }
        if (valid[2 * p + 1]) {
            long long rb = ra + THREADS;
            lsum += sb;
            __stcs((float4*)(out + rb * DD),     make_float4(ob[0], ob[1], ob[2], ob[3]));
            __stcs((float4*)(out + rb * DD + 4), make_float4(ob[4], ob[5], ob[6], ob[7]));
        }
    }

    // warp-aggregated histogram (integer-exact)
#pragma unroll
    for (int r = 0; r < RPT; r++) {
        unsigned int key = valid[r] ? (unsigned int)bi[r] : 0xFFFFFFFFu;
        unsigned int grp = __match_any_sync(0xffffffffu, key);
        bool leader = ((grp & ((1u << lane) - 1u)) == 0u);
        if (valid[r] && leader) atomicAdd(&s_cnt[bi[r]], (unsigned int)__popc(grp));
    }

    // ---- block reductions -> global accumulators ----
#pragma unroll
    for (int off = 16; off; off >>= 1)
        lsum += __shfl_down_sync(0xffffffffu, lsum, off);
    if ((tid & 31) == 0) s_red[tid >> 5] = (double)lsum;
    __syncthreads();
    if (tid == 0) {
        double t = 0.0;
#pragma unroll
        for (int w = 0; w < THREADS / 32; w++) t += s_red[w];
        atomicAdd(&g_sum, t);
    }
    if (tid < KC) {
        unsigned int c = s_cnt[tid];
        if (c) atomicAdd(&g_counts[tid], c);
    }

    // ---- last-block finalize (threadfence + ticket pattern) ----
    __syncthreads();                 // all atomics above issued
    if (tid == 0) {
        __threadfence();             // make this block's contributions device-visible
        unsigned int ticket = atomicAdd(&g_done, 1u);
        s_islast = (ticket == gridDim.x - 1) ? 1 : 0;
    }
    __syncthreads();

    if (s_islast && tid < 32) {
        unsigned int cnt = g_counts[tid];
        double p = (double)cnt / (double)nrows;
        double term = p * log(p + 1e-10);
#pragma unroll
        for (int off = 16; off; off >>= 1)
            term += __shfl_down_sync(0xffffffffu, term, off);
        if (tid == 0) {
            double s = atomicAdd(&g_sum, 0.0);   // atomic read
            if (write_scalars) {
                out[ndelem]     = (float)((s * 1.25) / (double)ndelem);
                out[ndelem + 1] = (float)exp(-term);
            }
            g_sum = 0.0;                          // reset for next graph replay
        }
        g_counts[tid] = 0u;
        __threadfence();
        if (tid == 0) g_done = 0u;
    }
}

extern "C" void kernel_launch(void* const* d_in, const int* in_sizes, int n_in,
                              void* d_out, int out_size) {
    const float* z  = (const float*)d_in[0];
    const float* cb = (const float*)d_in[1];
    float* out = (float*)d_out;

    int nrows = in_sizes[0] / DD;
    long long ndelem = (long long)nrows * DD;
    int blocks = (nrows + THREADS * RPT - 1) / (THREADS * RPT);
    int write_scalars = ((long long)out_size >= ndelem + 2) ? 1 : 0;

    vq_fused<<<blocks, THREADS>>>(z, cb, out, nrows, ndelem, write_scalars);
}

// round 10
// speedup vs baseline: 1.0644x; 1.0644x over previous
#include <cuda_runtime.h>
#include <math.h>

#define THREADS 256
#define RPT 4          // rows per thread
#define KC 32          // codebook size
#define DD 8           // codebook dim

__device__ double g_sum;                 // zero-init at load; reset by last block each run
__device__ unsigned int g_counts[KC];
__device__ unsigned int g_done;

static __device__ __forceinline__ unsigned long long pk2(float lo, float hi) {
    unsigned long long r;
    asm("mov.b64 %0, {%1,%2};" : "=l"(r) : "f"(lo), "f"(hi));
    return r;
}
static __device__ __forceinline__ void upk2(unsigned long long v, float& lo, float& hi) {
    asm("mov.b64 {%0,%1}, %2;" : "=f"(lo), "=f"(hi) : "l"(v));
}
// packed f32x2 fma: d.lo = a.lo*b.lo + c.lo ; d.hi = a.hi*b.hi + c.hi
static __device__ __forceinline__ unsigned long long ffma2(unsigned long long a,
                                                           unsigned long long b,
                                                           unsigned long long c) {
    unsigned long long r;
    asm("fma.rn.f32x2 %0, %1, %2, %3;" : "=l"(r) : "l"(a), "l"(b), "l"(c));
    return r;
}

__global__ __launch_bounds__(THREADS) void vq_fused(
    const float* __restrict__ z, const float* __restrict__ cb,
    float* __restrict__ out, int nrows, long long ndelem, int write_scalars)
{
    // Dim-packed codebook: s_mk[k][0..7] = -2*c_d (natural order -> f32x2 pairs
    // read as 2x LDS.128), s_mk[k][8] = ||c||^2. Stride 12 floats keeps rows
    // 16B-aligned. Broadcast reads: 9 wavefronts per k (vs 18 duplicated).
    __shared__ float s_mk[KC][12];
    __shared__ float2 s_cpair[KC][5];               // raw code row, stride 5 -> bank-safe gather
    __shared__ unsigned int s_cnt[KC];
    __shared__ double s_red[THREADS / 32];
    __shared__ int s_islast;

    const int tid = threadIdx.x;
    const int lane = tid & 31;

    if (tid < KC) {
        float cn = 0.f;
#pragma unroll
        for (int d = 0; d < DD; d++) {
            float v = cb[tid * DD + d];
            s_mk[tid][d] = -2.f * v;
            cn = fmaf(v, v, cn);
            if ((d & 1) == 0) s_cpair[tid][d >> 1].x = v;
            else              s_cpair[tid][d >> 1].y = v;
        }
        s_mk[tid][8] = cn;
        s_cnt[tid] = 0u;
    }
    __syncthreads();

    const long long base = (long long)blockIdx.x * (THREADS * RPT) + tid;

    // ---- load RPT rows; float4 pairs ARE the dim-packed f32x2 registers (no movs) ----
    unsigned long long zr[RPT][4];   // zr[r] = {(z0,z1),(z2,z3),(z4,z5),(z6,z7)}
    bool valid[RPT];
#pragma unroll
    for (int r = 0; r < RPT; ++r) {
        long long row = base + (long long)r * THREADS;
        valid[r] = (row < nrows);
        long long lr = valid[r] ? row : 0;
        float4 a0 = *(const float4*)(z + lr * DD);
        float4 a1 = *(const float4*)(z + lr * DD + 4);
        ulonglong2 u0 = *(ulonglong2*)&a0;   // u0.x=(z0,z1) u0.y=(z2,z3)
        ulonglong2 u1 = *(ulonglong2*)&a1;
        zr[r][0] = u0.x; zr[r][1] = u0.y;
        zr[r][2] = u1.x; zr[r][3] = u1.y;
    }

    float best[RPT];
    int   bi[RPT];
#pragma unroll
    for (int i = 0; i < RPT; i++) { best[i] = 3.4e38f; bi[i] = 0; }

    // ---- argmin over 32 codes: dist-z2 = ||c||^2 + sum((-2c_d) z_d)
    //      packed over the DIM axis; horizontal add at the end of each chain ----
#pragma unroll 2
    for (int k = 0; k < KC; k++) {
        ulonglong2 A = *(const ulonglong2*)&s_mk[k][0];  // (m0,m1),(m2,m3)
        ulonglong2 B = *(const ulonglong2*)&s_mk[k][4];  // (m4,m5),(m6,m7)
        float cn = s_mk[k][8];
        unsigned long long init = pk2(cn, 0.f);
#pragma unroll
        for (int r = 0; r < RPT; r++) {
            unsigned long long acc = ffma2(zr[r][0], A.x, init);
            acc = ffma2(zr[r][1], A.y, acc);
            acc = ffma2(zr[r][2], B.x, acc);
            acc = ffma2(zr[r][3], B.y, acc);
            float lo, hi;
            upk2(acc, lo, hi);
            float d = lo + hi;
            if (d < best[r]) { best[r] = d; bi[r] = k; }
        }
    }

    // ---- epilogue: explicit loss Σ(c−z)^2 (no cancellation), out = z + (c − z) ----
    float lsum = 0.f;
#pragma unroll
    for (int r = 0; r < RPT; r++) {
        if (!valid[r]) continue;
        const int b = bi[r];
        float2 c0 = s_cpair[b][0], c1 = s_cpair[b][1],
               c2 = s_cpair[b][2], c3 = s_cpair[b][3];
        float zv[DD];
        upk2(zr[r][0], zv[0], zv[1]);
        upk2(zr[r][1], zv[2], zv[3]);
        upk2(zr[r][2], zv[4], zv[5]);
        upk2(zr[r][3], zv[6], zv[7]);
        float cv[DD] = {c0.x, c0.y, c1.x, c1.y, c2.x, c2.y, c3.x, c3.y};
        float ov[DD];
        float s = 0.f;
#pragma unroll
        for (int d = 0; d < DD; d++) {
            float df = cv[d] - zv[d];
            ov[d] = zv[d] + df;       // z + (z_q - z), matches reference FP order
            s = fmaf(df, df, s);
        }
        lsum += s;
        long long row = base + (long long)r * THREADS;
        *(float4*)(out + row * DD)     = make_float4(ov[0], ov[1], ov[2], ov[3]);
        *(float4*)(out + row * DD + 4) = make_float4(ov[4], ov[5], ov[6], ov[7]);
    }

    // warp-aggregated histogram (integer-exact)
#pragma unroll
    for (int r = 0; r < RPT; r++) {
        unsigned int key = valid[r] ? (unsigned int)bi[r] : 0xFFFFFFFFu;
        unsigned int grp = __match_any_sync(0xffffffffu, key);
        bool leader = ((grp & ((1u << lane) - 1u)) == 0u);
        if (valid[r] && leader) atomicAdd(&s_cnt[bi[r]], (unsigned int)__popc(grp));
    }

    // ---- block reductions -> global accumulators ----
#pragma unroll
    for (int off = 16; off; off >>= 1)
        lsum += __shfl_down_sync(0xffffffffu, lsum, off);
    if ((tid & 31) == 0) s_red[tid >> 5] = (double)lsum;
    __syncthreads();
    if (tid == 0) {
        double t = 0.0;
#pragma unroll
        for (int w = 0; w < THREADS / 32; w++) t += s_red[w];
        atomicAdd(&g_sum, t);
    }
    if (tid < KC) {
        unsigned int c = s_cnt[tid];
        if (c) atomicAdd(&g_counts[tid], c);
    }

    // ---- last-block finalize (threadfence + ticket pattern) ----
    __syncthreads();                 // all atomics above issued
    if (tid == 0) {
        __threadfence();             // make this block's contributions device-visible
        unsigned int ticket = atomicAdd(&g_done, 1u);
        s_islast = (ticket == gridDim.x - 1) ? 1 : 0;
    }
    __syncthreads();

    if (s_islast && tid < 32) {
        unsigned int cnt = g_counts[tid];
        double p = (double)cnt / (double)nrows;
        double term = p * log(p + 1e-10);
#pragma unroll
        for (int off = 16; off; off >>= 1)
            term += __shfl_down_sync(0xffffffffu, term, off);
        if (tid == 0) {
            double s = atomicAdd(&g_sum, 0.0);   // atomic read
            if (write_scalars) {
                out[ndelem]     = (float)((s * 1.25) / (double)ndelem);
                out[ndelem + 1] = (float)exp(-term);
            }
            g_sum = 0.0;                          // reset for next graph replay
        }
        g_counts[tid] = 0u;
        __threadfence();
        if (tid == 0) g_done = 0u;
    }
}

extern "C" void kernel_launch(void* const* d_in, const int* in_sizes, int n_in,
                              void* d_out, int out_size) {
    const float* z  = (const float*)d_in[0];
    const float* cb = (const float*)d_in[1];
    float* out = (float*)d_out;

    int nrows = in_sizes[0] / DD;
    long long ndelem = (long long)nrows * DD;
    int blocks = (nrows + THREADS * RPT - 1) / (THREADS * RPT);
    int write_scalars = ((long long)out_size >= ndelem + 2) ? 1 : 0;

    vq_fused<<<blocks, THREADS>>>(z, cb, out, nrows, ndelem, write_scalars);
}